// round 1
// baseline (speedup 1.0000x reference)
#include <cuda_runtime.h>

#define Wd 512
#define Hd 256
#define Bd 4
#define HW (Hd*Wd)
#define NP (Bd*HW)
#define TX 32
#define TY 8
#define HALO 2
#define SWd (TX+2*HALO)   // 36
#define SHd (TY+2*HALO)   // 12

// Scratch (no cudaMalloc allowed): normalized weights (25 planes) + ping-pong fields
__device__ float g_wn[25*NP];   // 52.4 MB
__device__ float g_PA[3*NP];    // 6.3 MB
__device__ float g_PB[3*NP];    // 6.3 MB

// Fused kernel: compute bilateral weights (iteration-invariant), store wn = w/sum(w),
// and apply the FIRST smoothing iteration: P1 = P0 + imp0.
__global__ __launch_bounds__(256) void k_pre(const float* __restrict__ pts,
                                             const float* __restrict__ nrm,
                                             float* __restrict__ P1)
{
    __shared__ float sPx[SHd][SWd], sPy[SHd][SWd], sPz[SHd][SWd];
    __shared__ float sNx[SHd][SWd], sNy[SHd][SWd], sNz[SHd][SWd], sD[SHd][SWd];
    const int b  = blockIdx.z;
    const int x0 = blockIdx.x*TX, y0 = blockIdx.y*TY;
    const float* pb = pts + b*3*HW;
    const float* nb = nrm + b*3*HW;

    for (int i = threadIdx.y*TX + threadIdx.x; i < SWd*SHd; i += TX*TY) {
        int cy = i/SWd, cx = i - cy*SWd;
        int gx = x0+cx-HALO, gy = y0+cy-HALO;
        float px=0.f,py=0.f,pz=0.f,nx=0.f,ny=0.f,nz=0.f;
        if ((unsigned)gx < Wd && (unsigned)gy < Hd) {
            int o = gy*Wd + gx;
            px = pb[o]; py = pb[o+HW]; pz = pb[o+2*HW];
            nx = nb[o]; ny = nb[o+HW]; nz = nb[o+2*HW];
        }
        sPx[cy][cx]=px; sPy[cy][cx]=py; sPz[cy][cx]=pz;
        sNx[cy][cx]=nx; sNy[cy][cx]=ny; sNz[cy][cx]=nz;
        sD[cy][cx] = px*nx + py*ny + pz*nz;
    }
    __syncthreads();

    const int tx = threadIdx.x, ty = threadIdx.y;
    const int cx = tx+HALO,   cy = ty+HALO;
    const float pix_ = sPx[cy][cx], piy = sPy[cy][cx], piz = sPz[cy][cx];
    const float nix  = sNx[cy][cx], niy = sNy[cy][cx], niz = sNz[cy][cx];

    // Pass 1: squared distances + max (sigma_c)
    float wv[25];
    float maxn2 = 0.f;
    #pragma unroll
    for (int k = 0; k < 25; k++) {
        int dy = k/5 - 2, dx = k%5 - 2;
        float a = sPx[cy+dy][cx+dx] - pix_;
        float bq= sPy[cy+dy][cx+dx] - piy;
        float c = sPz[cy+dy][cx+dx] - piz;
        float d2 = a*a + bq*bq + c*c;
        wv[k] = d2;
        maxn2 = fmaxf(maxn2, d2);
    }
    float sig    = sqrtf(maxn2)*0.2f + 1e-5f;
    float nscale = -0.5f/(sig*sig);

    // Pass 2: fused exp( -n2/(2 sig^2) - 4.5 (1-cos)^2 )
    float wsum = 0.f;
    #pragma unroll
    for (int k = 0; k < 25; k++) {
        int dy = k/5 - 2, dx = k%5 - 2;
        float cosv = nix*sNx[cy+dy][cx+dx] + niy*sNy[cy+dy][cx+dx] + niz*sNz[cy+dy][cx+dx];
        float e = 1.f - cosv;
        float w = __expf(wv[k]*nscale - 4.5f*e*e);
        wv[k] = w;
        wsum += w;
    }
    float invsum = 1.f/wsum;

    // Pass 3: store normalized weights + first iteration improvement
    const int gx = x0+tx, gy = y0+ty;
    const int pixid = (b*Hd + gy)*Wd + gx;
    float ix=0.f, iy=0.f, iz=0.f;
    #pragma unroll
    for (int k = 0; k < 25; k++) {
        int dy = k/5 - 2, dx = k%5 - 2;
        float wn = wv[k]*invsum;
        g_wn[k*NP + pixid] = wn;
        float Nx = sNx[cy+dy][cx+dx], Ny = sNy[cy+dy][cx+dx], Nz = sNz[cy+dy][cx+dx];
        float dot = sD[cy+dy][cx+dx] - (Nx*pix_ + Ny*piy + Nz*piz);
        float t = wn*dot;
        ix += t*Nx; iy += t*Ny; iz += t*Nz;
    }
    const int o = b*3*HW + gy*Wd + gx;
    P1[o]      = pix_ + ix;
    P1[o+HW]   = piy  + iy;
    P1[o+2*HW] = piz  + iz;
}

// Smoothing iteration: P_out = P_cur + imp(P_cur), weights read from g_wn.
// LAST applies the sign(|pts_orig|) mask and writes the final output.
template<bool LAST>
__global__ __launch_bounds__(256) void k_iter(const float* __restrict__ Pcur,
                                              const float* __restrict__ nrm,
                                              const float* __restrict__ ptsOrig,
                                              float* __restrict__ Pout)
{
    __shared__ float sNx[SHd][SWd], sNy[SHd][SWd], sNz[SHd][SWd], sD[SHd][SWd];
    const int b  = blockIdx.z;
    const int x0 = blockIdx.x*TX, y0 = blockIdx.y*TY;
    const float* pb = Pcur + b*3*HW;
    const float* nb = nrm  + b*3*HW;

    for (int i = threadIdx.y*TX + threadIdx.x; i < SWd*SHd; i += TX*TY) {
        int cy = i/SWd, cx = i - cy*SWd;
        int gx = x0+cx-HALO, gy = y0+cy-HALO;
        float px=0.f,py=0.f,pz=0.f,nx=0.f,ny=0.f,nz=0.f;
        if ((unsigned)gx < Wd && (unsigned)gy < Hd) {
            int o = gy*Wd + gx;
            px = pb[o]; py = pb[o+HW]; pz = pb[o+2*HW];
            nx = nb[o]; ny = nb[o+HW]; nz = nb[o+2*HW];
        }
        sNx[cy][cx]=nx; sNy[cy][cx]=ny; sNz[cy][cx]=nz;
        sD[cy][cx] = px*nx + py*ny + pz*nz;
    }
    __syncthreads();

    const int tx = threadIdx.x, ty = threadIdx.y;
    const int cx = tx+HALO,   cy = ty+HALO;
    const int gx = x0+tx,     gy = y0+ty;
    const int o  = b*3*HW + gy*Wd + gx;
    const float pix_ = Pcur[o], piy = Pcur[o+HW], piz = Pcur[o+2*HW];  // L1 hits (just loaded)
    const int pixid = (b*Hd + gy)*Wd + gx;

    float ix=0.f, iy=0.f, iz=0.f;
    #pragma unroll
    for (int k = 0; k < 25; k++) {
        int dy = k/5 - 2, dx = k%5 - 2;
        float wn = g_wn[k*NP + pixid];
        float Nx = sNx[cy+dy][cx+dx], Ny = sNy[cy+dy][cx+dx], Nz = sNz[cy+dy][cx+dx];
        float dot = sD[cy+dy][cx+dx] - (Nx*pix_ + Ny*piy + Nz*piz);
        float t = wn*dot;
        ix += t*Nx; iy += t*Ny; iz += t*Nz;
    }
    float ox = pix_+ix, oy = piy+iy, oz = piz+iz;
    if (LAST) {
        ox = (ptsOrig[o]      != 0.f) ? ox : 0.f;
        oy = (ptsOrig[o+HW]   != 0.f) ? oy : 0.f;
        oz = (ptsOrig[o+2*HW] != 0.f) ? oz : 0.f;
    }
    Pout[o] = ox; Pout[o+HW] = oy; Pout[o+2*HW] = oz;
}

extern "C" void kernel_launch(void* const* d_in, const int* in_sizes, int n_in,
                              void* d_out, int out_size)
{
    const float* pts = (const float*)d_in[0];
    const float* nrm = (const float*)d_in[1];
    float* out = (float*)d_out;

    float *PA, *PB;
    cudaGetSymbolAddress((void**)&PA, g_PA);
    cudaGetSymbolAddress((void**)&PB, g_PB);

    dim3 block(TX, TY);
    dim3 grid(Wd/TX, Hd/TY, Bd);   // 16 x 32 x 4

    k_pre<<<grid, block>>>(pts, nrm, PA);                 // weights + iteration 1
    k_iter<false><<<grid, block>>>(PA, nrm, pts, PB);     // iteration 2
    k_iter<true ><<<grid, block>>>(PB, nrm, pts, out);    // iteration 3 + mask
}

// round 2
// speedup vs baseline: 1.1171x; 1.1171x over previous
#include <cuda_runtime.h>

#define Wd 512
#define Hd 256
#define Bd 4
#define HW (Hd*Wd)
#define NP (Bd*HW)
#define TX 32
#define TY 8
#define HALO 2
#define SWd (TX+2*HALO)   // 36
#define SHd (TY+2*HALO)   // 12

// Scratch (no cudaMalloc allowed)
__device__ float g_w[25*NP];    // unnormalized weights, 52.4 MB
__device__ float g_is[NP];      // per-pixel 1/sum(w), 2.1 MB
__device__ float g_PA[3*NP];    // ping
__device__ float g_PB[3*NP];    // pong

// Fused: bilateral weights (iteration-invariant) stored unnormalized + invsum,
// and first smoothing iteration P1 = P0 + imp0.
__global__ __launch_bounds__(256,2) void k_pre(const float* __restrict__ pts,
                                               const float* __restrict__ nrm,
                                               float* __restrict__ P1)
{
    __shared__ float4 sP[SHd][SWd];    // (Px,Py,Pz,_)
    __shared__ float4 sND[SHd][SWd];   // (Nx,Ny,Nz,D)
    const int b  = blockIdx.z;
    const int x0 = blockIdx.x*TX, y0 = blockIdx.y*TY;
    const float* pb = pts + b*3*HW;
    const float* nb = nrm + b*3*HW;

    for (int i = threadIdx.y*TX + threadIdx.x; i < SWd*SHd; i += TX*TY) {
        int cy = i/SWd, cx = i - cy*SWd;
        int gx = x0+cx-HALO, gy = y0+cy-HALO;
        float px=0.f,py=0.f,pz=0.f,nx=0.f,ny=0.f,nz=0.f;
        if ((unsigned)gx < Wd && (unsigned)gy < Hd) {
            int o = gy*Wd + gx;
            px = pb[o]; py = pb[o+HW]; pz = pb[o+2*HW];
            nx = nb[o]; ny = nb[o+HW]; nz = nb[o+2*HW];
        }
        sP[cy][cx]  = make_float4(px,py,pz,0.f);
        sND[cy][cx] = make_float4(nx,ny,nz, px*nx + py*ny + pz*nz);
    }
    __syncthreads();

    const int tx = threadIdx.x, ty = threadIdx.y;
    const int cx = tx+HALO,   cy = ty+HALO;
    const float4 pc = sP[cy][cx];
    const float4 nc = sND[cy][cx];
    const float pix_ = pc.x, piy = pc.y, piz = pc.z;
    const float nix  = nc.x, niy = nc.y, niz = nc.z;

    // Pass 1: squared point distances + running max (for sigma_c)
    float wv[25];
    float maxn2 = 0.f;
    #pragma unroll
    for (int k = 0; k < 25; k++) {
        int dy = k/5 - 2, dx = k%5 - 2;
        float4 p = sP[cy+dy][cx+dx];
        float a = p.x - pix_, bq = p.y - piy, c = p.z - piz;
        float d2 = a*a + bq*bq + c*c;
        wv[k] = d2;
        maxn2 = fmaxf(maxn2, d2);
    }
    float sig    = sqrtf(maxn2)*0.2f + 1e-5f;
    float nscale = -0.5f/(sig*sig);

    // Pass 2 (merged): w = exp(nscale*d2 - 4.5*(1-cos)^2), store raw w,
    // accumulate unnormalized improvement in the same loop.
    const int gx = x0+tx, gy = y0+ty;
    const int pixid = (b*Hd + gy)*Wd + gx;
    float wsum = 0.f, ix=0.f, iy=0.f, iz=0.f;
    #pragma unroll
    for (int k = 0; k < 25; k++) {
        int dy = k/5 - 2, dx = k%5 - 2;
        float4 nd = sND[cy+dy][cx+dx];
        float cosv = nix*nd.x + niy*nd.y + niz*nd.z;
        float e = 1.f - cosv;
        float w = __expf(wv[k]*nscale - 4.5f*e*e);
        g_w[k*NP + pixid] = w;
        wsum += w;
        float dot = nd.w - (nd.x*pix_ + nd.y*piy + nd.z*piz);
        float t = w*dot;
        ix += t*nd.x; iy += t*nd.y; iz += t*nd.z;
    }
    float invsum = 1.f/wsum;
    g_is[pixid] = invsum;

    const int o = b*3*HW + gy*Wd + gx;
    P1[o]      = pix_ + ix*invsum;
    P1[o+HW]   = piy  + iy*invsum;
    P1[o+2*HW] = piz  + iz*invsum;
}

// Smoothing iteration using stored raw weights + invsum.
// LAST applies the sign(|pts_orig|) mask and writes the final output.
template<bool LAST>
__global__ __launch_bounds__(256) void k_iter(const float* __restrict__ Pcur,
                                              const float* __restrict__ nrm,
                                              const float* __restrict__ ptsOrig,
                                              float* __restrict__ Pout)
{
    __shared__ float4 sND[SHd][SWd];   // (Nx,Ny,Nz,D) with D = N·Pcur
    const int b  = blockIdx.z;
    const int x0 = blockIdx.x*TX, y0 = blockIdx.y*TY;
    const float* pb = Pcur + b*3*HW;
    const float* nb = nrm  + b*3*HW;

    for (int i = threadIdx.y*TX + threadIdx.x; i < SWd*SHd; i += TX*TY) {
        int cy = i/SWd, cx = i - cy*SWd;
        int gx = x0+cx-HALO, gy = y0+cy-HALO;
        float px=0.f,py=0.f,pz=0.f,nx=0.f,ny=0.f,nz=0.f;
        if ((unsigned)gx < Wd && (unsigned)gy < Hd) {
            int o = gy*Wd + gx;
            px = pb[o]; py = pb[o+HW]; pz = pb[o+2*HW];
            nx = nb[o]; ny = nb[o+HW]; nz = nb[o+2*HW];
        }
        sND[cy][cx] = make_float4(nx,ny,nz, px*nx + py*ny + pz*nz);
    }
    __syncthreads();

    const int tx = threadIdx.x, ty = threadIdx.y;
    const int cx = tx+HALO,   cy = ty+HALO;
    const int gx = x0+tx,     gy = y0+ty;
    const int o  = b*3*HW + gy*Wd + gx;
    const float pix_ = Pcur[o], piy = Pcur[o+HW], piz = Pcur[o+2*HW]; // L1 hits
    const int pixid = (b*Hd + gy)*Wd + gx;
    const float invsum = g_is[pixid];

    float ix=0.f, iy=0.f, iz=0.f;
    #pragma unroll
    for (int k = 0; k < 25; k++) {
        int dy = k/5 - 2, dx = k%5 - 2;
        float w = g_w[k*NP + pixid];
        float4 nd = sND[cy+dy][cx+dx];
        float dot = nd.w - (nd.x*pix_ + nd.y*piy + nd.z*piz);
        float t = w*dot;
        ix += t*nd.x; iy += t*nd.y; iz += t*nd.z;
    }
    float ox = pix_ + ix*invsum, oy = piy + iy*invsum, oz = piz + iz*invsum;
    if (LAST) {
        ox = (ptsOrig[o]      != 0.f) ? ox : 0.f;
        oy = (ptsOrig[o+HW]   != 0.f) ? oy : 0.f;
        oz = (ptsOrig[o+2*HW] != 0.f) ? oz : 0.f;
    }
    Pout[o] = ox; Pout[o+HW] = oy; Pout[o+2*HW] = oz;
}

extern "C" void kernel_launch(void* const* d_in, const int* in_sizes, int n_in,
                              void* d_out, int out_size)
{
    const float* pts = (const float*)d_in[0];
    const float* nrm = (const float*)d_in[1];
    float* out = (float*)d_out;

    float *PA, *PB;
    cudaGetSymbolAddress((void**)&PA, g_PA);
    cudaGetSymbolAddress((void**)&PB, g_PB);

    dim3 block(TX, TY);
    dim3 grid(Wd/TX, Hd/TY, Bd);   // 16 x 32 x 4

    k_pre<<<grid, block>>>(pts, nrm, PA);                 // weights + iteration 1
    k_iter<false><<<grid, block>>>(PA, nrm, pts, PB);     // iteration 2
    k_iter<true ><<<grid, block>>>(PB, nrm, pts, out);    // iteration 3 + mask
}